// round 11
// baseline (speedup 1.0000x reference)
#include <cuda_runtime.h>
#include <cuda_bf16.h>
#include <cstdint>

#define BB    2048
#define CC    9605
#define LL    8
#define NT    256
#define TOPK  16
#define TVAL  2.6f
#define CAP   1024
#define NW    (NT / 32)

#define ALPHA   0.5f
#define ALPHA1  0.05f
#define ALPHA2  2.0f
#define ALPHA3  5.0f
#define ALPHA_OTHER 0.3f

// Scratch (no cudaMalloc allowed)
__device__ float          g_partial[BB];
__device__ unsigned char  g_gbits[CC + 16];
__device__ unsigned short g_glist[LL * CC];  // group-major sorted class lists
__device__ int            g_goff[LL + 1];    // per-group offsets into g_glist
__device__ int            g_fA, g_fB;        // mask-dtype flags (idempotent atomicOr)
__device__ int            g_done;            // zero-init; reset by last block each call

__device__ __forceinline__ float sigm(float v) { return 1.0f / (1.0f + __expf(-v)); }

__device__ __forceinline__ float rankl(float x1, float x2) {
    float d = x2 - x1 + ALPHA1;
    float s = 1.0f / (1.0f + __expf(-ALPHA3 * d));
    return d > 0.0f ? ALPHA2 * s : s;
}

// ---------------------------------------------------------------------------
// prep_a (multi-block): classify mask dtype from byte pattern.
//   f32 1.0 -> bytes {00,00,80,3F}: some byte has a bit above bit0 -> word mode
//   i32 1   -> ones only at offset%4==0                            -> word mode
//   bool    -> 0x01 at arbitrary byte offsets                      -> byte mode
// ---------------------------------------------------------------------------
__global__ void prep_a_kernel(const unsigned char* __restrict__ mraw) {
    const unsigned int* mw = (const unsigned int*)mraw;
    unsigned int a = 0, bm = 0;
    int i = blockIdx.x * blockDim.x + threadIdx.x;
    const int n = (CC * LL) / 4;                 // 19210 words exact
    for (; i < n; i += gridDim.x * blockDim.x) {
        unsigned int wv = __ldg(mw + i);
        a  |= (wv & 0xFEFEFEFEu);   // any byte >= 2 anywhere
        bm |= (wv & 0x01010100u);   // bit0 set in bytes at offset%4 != 0
    }
    if (a)  atomicOr(&g_fA, 1);
    if (bm) atomicOr(&g_fB, 1);
}

// ---------------------------------------------------------------------------
// prep_b (multi-block): per-class membership byte.
// ---------------------------------------------------------------------------
__global__ void prep_b_kernel(const unsigned char* __restrict__ mraw) {
    const int bytemode = (!g_fA) && g_fB;
    const unsigned int* mw = (const unsigned int*)mraw;
    int c = blockIdx.x * blockDim.x + threadIdx.x;
    if (c >= CC) return;
    unsigned int bits = 0;
    if (bytemode) {
        #pragma unroll
        for (int l = 0; l < LL; ++l)
            if (mraw[l * CC + c] != 0) bits |= (1u << l);
    } else {
        #pragma unroll
        for (int l = 0; l < LL; ++l)
            if (mw[l * CC + c] != 0u) bits |= (1u << l);
    }
    g_gbits[c] = (unsigned char)bits;
}

// ---------------------------------------------------------------------------
// prep_c (ONE block): group-major stable compaction.
// For each group l: sorted list of member classes; offsets in g_goff.
// ---------------------------------------------------------------------------
__global__ __launch_bounds__(1024) void prep_c_kernel() {
    __shared__ int s_wtot[32], s_wex[32];
    __shared__ int s_base, s_ctot;
    const int t = threadIdx.x, w = t >> 5, lane = t & 31;
    const unsigned fm = 0xFFFFFFFFu;
    if (t == 0) s_base = 0;
    __syncthreads();

    for (int l = 0; l < LL; ++l) {
        if (t == 0) g_goff[l] = s_base;
        for (int base = 0; base < CC; base += 1024) {
            int c = base + t;
            int ind = (c < CC) && ((g_gbits[c] >> l) & 1);
            unsigned int wm = __ballot_sync(fm, ind);
            int rank = __popc(wm & ((1u << lane) - 1u));
            if (lane == 0) s_wtot[w] = __popc(wm);
            __syncthreads();
            if (w == 0) {
                int v = s_wtot[lane];
                int inc = v;
                #pragma unroll
                for (int off = 1; off < 32; off <<= 1) {
                    int u = __shfl_up_sync(fm, inc, off);
                    if (lane >= off) inc += u;
                }
                s_wex[lane] = inc - v;             // exclusive warp offsets
                if (lane == 31) s_ctot = inc;      // chunk total
            }
            __syncthreads();
            if (ind) g_glist[s_base + s_wex[w] + rank] = (unsigned short)c;
            __syncthreads();
            if (t == 0) s_base += s_ctot;
            __syncthreads();
        }
    }
    if (t == 0) g_goff[LL] = s_base;
}

// ---------------------------------------------------------------------------
// row_kernel: one CTA per sample.
// Loop 1: coalesced stream (x float4, y/yn uint4; 2 packs/iter). Candidate
//   detection via pack-max + divergent atomic append (no warp collectives;
//   ragged trip counts are safe). y/yn positives via integer-OR nonzero test,
//   rare branch does scalar gbit lookups.
// Loop 2: group-major x-only gathers (L2-hot): 1 fmax per entry, gmax[l]
//   compile-time indexed. umax derived from gmax afterwards.
// Selection: order-invariant rank-count over candidates (exact, deterministic).
// Last CTA reduces the 2048 partials deterministically.
// ---------------------------------------------------------------------------
__global__ __launch_bounds__(NT) void row_kernel(const float* __restrict__ x,
                                                 const float* __restrict__ y,
                                                 const float* __restrict__ yn,
                                                 float* __restrict__ out) {
    __shared__ float s_cand[CAP];
    __shared__ float s_red[NT];
    __shared__ float s_gmax[NW][LL];
    __shared__ unsigned int s_gtb[NW], s_gnb[NW];
    __shared__ float s_t16;
    __shared__ int s_ncand, s_last;

    const int b = blockIdx.x, t = threadIdx.x, w = t >> 5, lane = t & 31;
    const size_t base = (size_t)b * CC;
    const float* __restrict__ xr = x + base;
    const float* __restrict__ yr = y + base;
    const float* __restrict__ nr = yn + base;

    // alignment: (b*9605) % 4 == b % 4  (9605 % 4 == 1)
    const int av = b & 3;
    const int p  = (4 - av) & 3;             // scalar peel count
    const int nv = (CC - p) >> 2;            // float4 count
    const int r  = (CC - p) & 3;             // scalar tail count

    if (t == 0) s_ncand = 0;
    __syncthreads();

    const float NI = __int_as_float(0xff800000);
    const unsigned fm = 0xFFFFFFFFu;
    unsigned int gtb = 0, gnb = 0;

    // ---- peel + tail (<= 5 elements; scalar, no collectives) ----
    if (t < p + r) {
        int idx = (t < p) ? t : (p + 4 * nv + (t - p));
        float xv = __ldg(xr + idx);
        if (xv > TVAL) {
            int pos = atomicAdd(&s_ncand, 1);
            if (pos < CAP) s_cand[pos] = xv;
        }
        unsigned int gb = g_gbits[idx];
        if (gb) {
            if (__ldg(yr + idx) > 0.0f) gtb |= gb;
            if (__ldg(nr + idx) > 0.0f) gnb |= gb;
        }
    }

    // ---- Loop 1: coalesced stream, 2 packs/iter, no collectives ----
    const float4* __restrict__ x4 = (const float4*)(xr + p);
    const uint4*  __restrict__ yu = (const uint4*)(yr + p);
    const uint4*  __restrict__ nu = (const uint4*)(nr + p);

    // candidate append: pack-max gate, then divergent atomic (rare)
    #define XBLK(XV)                                                           \
    {                                                                          \
        float _pm = fmaxf(fmaxf((XV).x, (XV).y), fmaxf((XV).z, (XV).w));       \
        if (_pm > TVAL) {                                                      \
            int _c = ((XV).x > TVAL) + ((XV).y > TVAL) +                       \
                     ((XV).z > TVAL) + ((XV).w > TVAL);                        \
            int _pos = atomicAdd(&s_ncand, _c);                                \
            if ((XV).x > TVAL) { if (_pos < CAP) s_cand[_pos] = (XV).x; ++_pos; } \
            if ((XV).y > TVAL) { if (_pos < CAP) s_cand[_pos] = (XV).y; ++_pos; } \
            if ((XV).z > TVAL) { if (_pos < CAP) s_cand[_pos] = (XV).z; ++_pos; } \
            if ((XV).w > TVAL) { if (_pos < CAP) s_cand[_pos] = (XV).w; ++_pos; } \
        }                                                                      \
    }

    // positive detection on binarized y/yn: nonzero bit pattern <=> 1.0f
    #define YBLK(YV, VI, DST)                                                  \
    {                                                                          \
        if (((YV).x | (YV).y | (YV).z | (YV).w) != 0u) {                       \
            int _ci = p + 4 * (VI);                                            \
            if ((YV).x) DST |= (unsigned int)g_gbits[_ci];                     \
            if ((YV).y) DST |= (unsigned int)g_gbits[_ci + 1];                 \
            if ((YV).z) DST |= (unsigned int)g_gbits[_ci + 2];                 \
            if ((YV).w) DST |= (unsigned int)g_gbits[_ci + 3];                 \
        }                                                                      \
    }

    for (int v = t; v < nv; v += 2 * NT) {
        const int vb = v + NT;
        const bool hb = (vb < nv);
        float4 xa = __ldg(x4 + v);
        uint4  ya = __ldcs(yu + v);
        uint4  na = __ldcs(nu + v);
        float4 xb;
        uint4  yb, nb;
        if (hb) { xb = __ldg(x4 + vb); yb = __ldcs(yu + vb); nb = __ldcs(nu + vb); }

        XBLK(xa)
        YBLK(ya, v, gtb)
        YBLK(na, v, gnb)
        if (hb) {
            XBLK(xb)
            YBLK(yb, vb, gtb)
            YBLK(nb, vb, gnb)
        }
    }
    #undef XBLK
    #undef YBLK

    // ---- Loop 2: group-major x gathers (L2-hot), 1 fmax per entry ----
    float gmax[LL];
    #pragma unroll
    for (int l = 0; l < LL; ++l) {
        const int s0 = __ldg(&g_goff[l]), e0 = __ldg(&g_goff[l + 1]);
        float m = NI;
        for (int i = s0 + t; i < e0; i += NT)
            m = fmaxf(m, __ldg(xr + (int)__ldg(&g_glist[i])));
        gmax[l] = m;
    }

    // ---- warp-reduce aggregates ----
    #pragma unroll
    for (int off = 16; off > 0; off >>= 1) {
        #pragma unroll
        for (int l = 0; l < LL; ++l)
            gmax[l] = fmaxf(gmax[l], __shfl_xor_sync(fm, gmax[l], off));
        gtb |= __shfl_xor_sync(fm, gtb, off);
        gnb |= __shfl_xor_sync(fm, gnb, off);
    }
    if (lane == 0) {
        #pragma unroll
        for (int l = 0; l < LL; ++l) s_gmax[w][l] = gmax[l];
        s_gtb[w] = gtb;
        s_gnb[w] = gnb;
    }
    __syncthreads();

    int nc = s_ncand;                            // true count of x > TVAL

    // ---- exact fallback (data-independent guarantee): rebuild candidates ----
    if (nc < TOPK || nc > CAP) {
        __syncthreads();                         // everyone done reading s_ncand
        if (t < 64) {
            float tk[TOPK];
            #pragma unroll
            for (int k = 0; k < TOPK; ++k) tk[k] = NI;
            for (int i = t; i < CC; i += 64) {
                float xv = __ldg(xr + i);
                if (xv > tk[TOPK - 1]) {
                    float _v = xv;
                    #pragma unroll
                    for (int k = 0; k < TOPK; ++k)
                        if (_v > tk[k]) { float _tmp = tk[k]; tk[k] = _v; _v = _tmp; }
                }
            }
            #pragma unroll
            for (int k = 0; k < TOPK; ++k) s_cand[t * TOPK + k] = tk[k];
        }
        __syncthreads();
        nc = 64 * TOPK;                          // row top-16 is within these 1024
    }

    // ---- rank-count selection: 16th-largest = v with #{>v} <= 15 < #{>=v} ----
    for (int i = t; i < nc; i += NT) {
        float v = s_cand[i];
        int cg = 0, ce = 0;
        for (int j = 0; j < nc; ++j) {
            float u = s_cand[j];                 // broadcast read, conflict-free
            cg += (u > v);
            ce += (u == v);
        }
        if (cg <= TOPK - 1 && cg + ce >= TOPK) s_t16 = v;   // unique value; benign race
    }
    __syncthreads();

    // ---- per-row loss (thread 0) ----
    if (t == 0) {
        float gmaxA[LL];
        #pragma unroll
        for (int l = 0; l < LL; ++l) gmaxA[l] = NI;
        unsigned int gtA = 0, gnA = 0;
        for (int wv = 0; wv < NW; ++wv) {
            #pragma unroll
            for (int l = 0; l < LL; ++l) gmaxA[l] = fmaxf(gmaxA[l], s_gmax[wv][l]);
            gtA |= s_gtb[wv];
            gnA |= s_gnb[wv];
        }
        float umaxA = NI;                        // union max = max over group maxes
        #pragma unroll
        for (int l = 0; l < LL; ++l) umaxA = fmaxf(umaxA, gmaxA[l]);

        float thres = fmaxf(sigm(s_t16), ALPHA_OTHER);

        float loss;
        if (gtA) {
            loss = 0.0f;
            #pragma unroll
            for (int l = 0; l < LL; ++l) {
                float gm = sigm(gmaxA[l]);
                loss += ((gtA >> l) & 1u) ? rankl(gm, thres)
                                          : rankl(thres, gm);
            }
        } else {
            float um = sigm(umaxA);
            float negs = 0.0f;                   // torch starts at 0
            if (gnA) {
                float nm = NI;
                #pragma unroll
                for (int l = 0; l < LL; ++l)
                    if ((gnA >> l) & 1u) nm = fmaxf(nm, gmaxA[l]);
                negs = sigm(nm);
            }
            loss = (1.0f - ALPHA) * rankl(thres, um) + ALPHA * rankl(thres, negs);
        }
        g_partial[b] = loss;
    }

    // ---- fused deterministic mean: last CTA reduces all partials ----
    if (t == 0) {
        __threadfence();
        int old = atomicAdd(&g_done, 1);
        s_last = (old == BB - 1);
    }
    __syncthreads();
    if (s_last) {
        float acc = 0.0f;
        for (int i = t; i < BB; i += NT) acc += g_partial[i];   // fixed order
        s_red[t] = acc;
        __syncthreads();
        for (int st = NT / 2; st > 0; st >>= 1) {
            if (t < st) s_red[t] += s_red[t + st];
            __syncthreads();
        }
        if (t == 0) { out[0] = s_red[0] / (float)BB; g_done = 0; }
    }
}

extern "C" void kernel_launch(void* const* d_in, const int* in_sizes, int n_in,
                              void* d_out, int out_size) {
    (void)in_sizes; (void)n_in; (void)out_size;
    const float*         x  = (const float*)d_in[0];
    const float*         y  = (const float*)d_in[1];
    const float*         yn = (const float*)d_in[2];
    const unsigned char* m  = (const unsigned char*)d_in[3];

    prep_a_kernel<<<4, 1024>>>(m);
    prep_b_kernel<<<(CC + 1023) / 1024, 1024>>>(m);
    prep_c_kernel<<<1, 1024>>>();
    row_kernel<<<BB, NT>>>(x, y, yn, (float*)d_out);
}

// round 12
// speedup vs baseline: 2.1436x; 2.1436x over previous
#include <cuda_runtime.h>
#include <cuda_bf16.h>
#include <cstdint>

#define BB    2048
#define CC    9605
#define LL    8
#define NT    256
#define TOPK  16
#define TVAL  2.6f
#define CAP   1024
#define NW    (NT / 32)

#define ALPHA   0.5f
#define ALPHA1  0.05f
#define ALPHA2  2.0f
#define ALPHA3  5.0f
#define ALPHA_OTHER 0.3f

// Scratch (no cudaMalloc allowed)
__device__ float          g_partial[BB];
__device__ unsigned char  g_gbits[CC + 16];
__device__ unsigned short g_glist[LL * CC];  // group-major class lists (UNORDERED)
__device__ int            g_gcnt[LL];        // per-group member counts (atomic)
__device__ int            g_fA, g_fB;        // mask-dtype flags (idempotent atomicOr)
__device__ int            g_done;            // zero-init; reset by last block each call

__device__ __forceinline__ float sigm(float v) { return 1.0f / (1.0f + __expf(-v)); }

__device__ __forceinline__ float rankl(float x1, float x2) {
    float d = x2 - x1 + ALPHA1;
    float s = 1.0f / (1.0f + __expf(-ALPHA3 * d));
    return d > 0.0f ? ALPHA2 * s : s;
}

// ---------------------------------------------------------------------------
// prep_a (multi-block): classify mask dtype from byte pattern; zero counters.
//   f32 1.0 -> bytes {00,00,80,3F}: some byte has a bit above bit0 -> word mode
//   i32 1   -> ones only at offset%4==0                            -> word mode
//   bool    -> 0x01 at arbitrary byte offsets                      -> byte mode
// Counter zeroing is stream-ordered before prep_b uses them.
// ---------------------------------------------------------------------------
__global__ void prep_a_kernel(const unsigned char* __restrict__ mraw) {
    if (blockIdx.x == 0 && threadIdx.x < LL) g_gcnt[threadIdx.x] = 0;
    const unsigned int* mw = (const unsigned int*)mraw;
    unsigned int a = 0, bm = 0;
    int i = blockIdx.x * blockDim.x + threadIdx.x;
    const int n = (CC * LL) / 4;                 // 19210 words exact
    for (; i < n; i += gridDim.x * blockDim.x) {
        unsigned int wv = __ldg(mw + i);
        a  |= (wv & 0xFEFEFEFEu);   // any byte >= 2 anywhere
        bm |= (wv & 0x01010100u);   // bit0 set in bytes at offset%4 != 0
    }
    if (a)  atomicOr(&g_fA, 1);
    if (bm) atomicOr(&g_fB, 1);
}

// ---------------------------------------------------------------------------
// prep_b (multi-block): per-class membership byte + UNORDERED group-major
// compaction via per-group atomic counters. List order varies across replays,
// but loop 2 only takes a set-max over each list -> bitwise-identical result.
// ---------------------------------------------------------------------------
__global__ void prep_b_kernel(const unsigned char* __restrict__ mraw) {
    const int bytemode = (!g_fA) && g_fB;
    const unsigned int* mw = (const unsigned int*)mraw;
    int c = blockIdx.x * blockDim.x + threadIdx.x;
    if (c >= CC) return;
    unsigned int bits = 0;
    if (bytemode) {
        #pragma unroll
        for (int l = 0; l < LL; ++l)
            if (mraw[l * CC + c] != 0) bits |= (1u << l);
    } else {
        #pragma unroll
        for (int l = 0; l < LL; ++l)
            if (mw[l * CC + c] != 0u) bits |= (1u << l);
    }
    g_gbits[c] = (unsigned char)bits;
    #pragma unroll
    for (int l = 0; l < LL; ++l) {
        if (bits & (1u << l)) {
            int pos = atomicAdd(&g_gcnt[l], 1);
            g_glist[l * CC + pos] = (unsigned short)c;
        }
    }
}

// ---------------------------------------------------------------------------
// row_kernel: one CTA per sample.
// Loop 1: coalesced stream (x float4, y/yn uint4; 2 packs/iter). Candidate
//   detection via pack-max + divergent atomic append (no warp collectives).
//   y/yn positives via integer-OR nonzero test; rare branch -> gbit lookups.
// Loop 2: group-major x-only gathers (L2-hot): 1 fmax per entry.
// Selection: order-invariant rank-count over candidates (exact, deterministic).
// Last CTA reduces the 2048 partials deterministically.
// ---------------------------------------------------------------------------
__global__ __launch_bounds__(NT) void row_kernel(const float* __restrict__ x,
                                                 const float* __restrict__ y,
                                                 const float* __restrict__ yn,
                                                 float* __restrict__ out) {
    __shared__ float s_cand[CAP];
    __shared__ float s_red[NT];
    __shared__ float s_gmax[NW][LL];
    __shared__ unsigned int s_gtb[NW], s_gnb[NW];
    __shared__ float s_t16;
    __shared__ int s_ncand, s_last;

    const int b = blockIdx.x, t = threadIdx.x, w = t >> 5, lane = t & 31;
    const size_t base = (size_t)b * CC;
    const float* __restrict__ xr = x + base;
    const float* __restrict__ yr = y + base;
    const float* __restrict__ nr = yn + base;

    // alignment: (b*9605) % 4 == b % 4  (9605 % 4 == 1)
    const int av = b & 3;
    const int p  = (4 - av) & 3;             // scalar peel count
    const int nv = (CC - p) >> 2;            // float4 count
    const int r  = (CC - p) & 3;             // scalar tail count

    if (t == 0) s_ncand = 0;
    __syncthreads();

    const float NI = __int_as_float(0xff800000);
    const unsigned fm = 0xFFFFFFFFu;
    unsigned int gtb = 0, gnb = 0;

    // ---- peel + tail (<= 5 elements; scalar, no collectives) ----
    if (t < p + r) {
        int idx = (t < p) ? t : (p + 4 * nv + (t - p));
        float xv = __ldg(xr + idx);
        if (xv > TVAL) {
            int pos = atomicAdd(&s_ncand, 1);
            if (pos < CAP) s_cand[pos] = xv;
        }
        unsigned int gb = g_gbits[idx];
        if (gb) {
            if (__ldg(yr + idx) > 0.0f) gtb |= gb;
            if (__ldg(nr + idx) > 0.0f) gnb |= gb;
        }
    }

    // ---- Loop 1: coalesced stream, 2 packs/iter, no collectives ----
    const float4* __restrict__ x4 = (const float4*)(xr + p);
    const uint4*  __restrict__ yu = (const uint4*)(yr + p);
    const uint4*  __restrict__ nu = (const uint4*)(nr + p);

    // candidate append: pack-max gate, then divergent atomic (rare)
    #define XBLK(XV)                                                           \
    {                                                                          \
        float _pm = fmaxf(fmaxf((XV).x, (XV).y), fmaxf((XV).z, (XV).w));       \
        if (_pm > TVAL) {                                                      \
            int _c = ((XV).x > TVAL) + ((XV).y > TVAL) +                       \
                     ((XV).z > TVAL) + ((XV).w > TVAL);                        \
            int _pos = atomicAdd(&s_ncand, _c);                                \
            if ((XV).x > TVAL) { if (_pos < CAP) s_cand[_pos] = (XV).x; ++_pos; } \
            if ((XV).y > TVAL) { if (_pos < CAP) s_cand[_pos] = (XV).y; ++_pos; } \
            if ((XV).z > TVAL) { if (_pos < CAP) s_cand[_pos] = (XV).z; ++_pos; } \
            if ((XV).w > TVAL) { if (_pos < CAP) s_cand[_pos] = (XV).w; ++_pos; } \
        }                                                                      \
    }

    // positive detection on binarized y/yn: nonzero bit pattern <=> 1.0f
    #define YBLK(YV, VI, DST)                                                  \
    {                                                                          \
        if (((YV).x | (YV).y | (YV).z | (YV).w) != 0u) {                       \
            int _ci = p + 4 * (VI);                                            \
            if ((YV).x) DST |= (unsigned int)g_gbits[_ci];                     \
            if ((YV).y) DST |= (unsigned int)g_gbits[_ci + 1];                 \
            if ((YV).z) DST |= (unsigned int)g_gbits[_ci + 2];                 \
            if ((YV).w) DST |= (unsigned int)g_gbits[_ci + 3];                 \
        }                                                                      \
    }

    for (int v = t; v < nv; v += 2 * NT) {
        const int vb = v + NT;
        const bool hb = (vb < nv);
        float4 xa = __ldg(x4 + v);
        uint4  ya = __ldcs(yu + v);
        uint4  na = __ldcs(nu + v);
        float4 xb;
        uint4  yb, nb;
        if (hb) { xb = __ldg(x4 + vb); yb = __ldcs(yu + vb); nb = __ldcs(nu + vb); }

        XBLK(xa)
        YBLK(ya, v, gtb)
        YBLK(na, v, gnb)
        if (hb) {
            XBLK(xb)
            YBLK(yb, vb, gtb)
            YBLK(nb, vb, gnb)
        }
    }
    #undef XBLK
    #undef YBLK

    // ---- Loop 2: group-major x gathers (L2-hot), 1 fmax per entry ----
    float gmax[LL];
    #pragma unroll
    for (int l = 0; l < LL; ++l) {
        const int cnt = __ldg(&g_gcnt[l]);
        const unsigned short* __restrict__ lst = g_glist + l * CC;
        float m = NI;
        for (int i = t; i < cnt; i += NT)
            m = fmaxf(m, __ldg(xr + (int)__ldg(lst + i)));
        gmax[l] = m;
    }

    // ---- warp-reduce aggregates ----
    #pragma unroll
    for (int off = 16; off > 0; off >>= 1) {
        #pragma unroll
        for (int l = 0; l < LL; ++l)
            gmax[l] = fmaxf(gmax[l], __shfl_xor_sync(fm, gmax[l], off));
        gtb |= __shfl_xor_sync(fm, gtb, off);
        gnb |= __shfl_xor_sync(fm, gnb, off);
    }
    if (lane == 0) {
        #pragma unroll
        for (int l = 0; l < LL; ++l) s_gmax[w][l] = gmax[l];
        s_gtb[w] = gtb;
        s_gnb[w] = gnb;
    }
    __syncthreads();

    int nc = s_ncand;                            // true count of x > TVAL

    // ---- exact fallback (data-independent guarantee): rebuild candidates ----
    if (nc < TOPK || nc > CAP) {
        __syncthreads();                         // everyone done reading s_ncand
        if (t < 64) {
            float tk[TOPK];
            #pragma unroll
            for (int k = 0; k < TOPK; ++k) tk[k] = NI;
            for (int i = t; i < CC; i += 64) {
                float xv = __ldg(xr + i);
                if (xv > tk[TOPK - 1]) {
                    float _v = xv;
                    #pragma unroll
                    for (int k = 0; k < TOPK; ++k)
                        if (_v > tk[k]) { float _tmp = tk[k]; tk[k] = _v; _v = _tmp; }
                }
            }
            #pragma unroll
            for (int k = 0; k < TOPK; ++k) s_cand[t * TOPK + k] = tk[k];
        }
        __syncthreads();
        nc = 64 * TOPK;                          // row top-16 is within these 1024
    }

    // ---- rank-count selection: 16th-largest = v with #{>v} <= 15 < #{>=v} ----
    for (int i = t; i < nc; i += NT) {
        float v = s_cand[i];
        int cg = 0, ce = 0;
        for (int j = 0; j < nc; ++j) {
            float u = s_cand[j];                 // broadcast read, conflict-free
            cg += (u > v);
            ce += (u == v);
        }
        if (cg <= TOPK - 1 && cg + ce >= TOPK) s_t16 = v;   // unique value; benign race
    }
    __syncthreads();

    // ---- per-row loss (thread 0) ----
    if (t == 0) {
        float gmaxA[LL];
        #pragma unroll
        for (int l = 0; l < LL; ++l) gmaxA[l] = NI;
        unsigned int gtA = 0, gnA = 0;
        for (int wv = 0; wv < NW; ++wv) {
            #pragma unroll
            for (int l = 0; l < LL; ++l) gmaxA[l] = fmaxf(gmaxA[l], s_gmax[wv][l]);
            gtA |= s_gtb[wv];
            gnA |= s_gnb[wv];
        }
        float umaxA = NI;                        // union max = max over group maxes
        #pragma unroll
        for (int l = 0; l < LL; ++l) umaxA = fmaxf(umaxA, gmaxA[l]);

        float thres = fmaxf(sigm(s_t16), ALPHA_OTHER);

        float loss;
        if (gtA) {
            loss = 0.0f;
            #pragma unroll
            for (int l = 0; l < LL; ++l) {
                float gm = sigm(gmaxA[l]);
                loss += ((gtA >> l) & 1u) ? rankl(gm, thres)
                                          : rankl(thres, gm);
            }
        } else {
            float um = sigm(umaxA);
            float negs = 0.0f;                   // torch starts at 0
            if (gnA) {
                float nm = NI;
                #pragma unroll
                for (int l = 0; l < LL; ++l)
                    if ((gnA >> l) & 1u) nm = fmaxf(nm, gmaxA[l]);
                negs = sigm(nm);
            }
            loss = (1.0f - ALPHA) * rankl(thres, um) + ALPHA * rankl(thres, negs);
        }
        g_partial[b] = loss;
    }

    // ---- fused deterministic mean: last CTA reduces all partials ----
    if (t == 0) {
        __threadfence();
        int old = atomicAdd(&g_done, 1);
        s_last = (old == BB - 1);
    }
    __syncthreads();
    if (s_last) {
        float acc = 0.0f;
        for (int i = t; i < BB; i += NT) acc += g_partial[i];   // fixed order
        s_red[t] = acc;
        __syncthreads();
        for (int st = NT / 2; st > 0; st >>= 1) {
            if (t < st) s_red[t] += s_red[t + st];
            __syncthreads();
        }
        if (t == 0) { out[0] = s_red[0] / (float)BB; g_done = 0; }
    }
}

extern "C" void kernel_launch(void* const* d_in, const int* in_sizes, int n_in,
                              void* d_out, int out_size) {
    (void)in_sizes; (void)n_in; (void)out_size;
    const float*         x  = (const float*)d_in[0];
    const float*         y  = (const float*)d_in[1];
    const float*         yn = (const float*)d_in[2];
    const unsigned char* m  = (const unsigned char*)d_in[3];

    prep_a_kernel<<<4, 1024>>>(m);
    prep_b_kernel<<<(CC + 1023) / 1024, 1024>>>(m);
    row_kernel<<<BB, NT>>>(x, y, yn, (float*)d_out);
}

// round 13
// speedup vs baseline: 2.1927x; 1.0229x over previous
#include <cuda_runtime.h>
#include <cuda_bf16.h>
#include <cstdint>

#define BB    2048
#define CC    9605
#define LL    8
#define NT    256
#define TOPK  16
#define TVAL  2.6f
#define CAP   1024
#define NW    (NT / 32)

#define ALPHA   0.5f
#define ALPHA1  0.05f
#define ALPHA2  2.0f
#define ALPHA3  5.0f
#define ALPHA_OTHER 0.3f

// Scratch (no cudaMalloc allowed)
__device__ float          g_partial[BB];
__device__ unsigned char  g_gbits[CC + 16];
__device__ unsigned short g_glist[LL * CC];  // group-major class lists (UNORDERED)
__device__ int            g_gcnt[LL];        // zero-init; reset by row_kernel tail
__device__ int            g_done;            // zero-init; reset by row_kernel tail

__device__ __forceinline__ float sigm(float v) { return 1.0f / (1.0f + __expf(-v)); }

__device__ __forceinline__ float rankl(float x1, float x2) {
    float d = x2 - x1 + ALPHA1;
    float s = 1.0f / (1.0f + __expf(-ALPHA3 * d));
    return d > 0.0f ? ALPHA2 * s : s;
}

// ---------------------------------------------------------------------------
// prep (ONE launch, multi-block): each block redundantly classifies the mask
// dtype (uint4 scan of all 76840 bytes), then builds its slice of per-class
// membership bytes + UNORDERED group-major compaction via atomic counters.
//   f32 1.0 -> bytes {00,00,80,3F}: some byte has a bit above bit0 -> word mode
//   i32 1   -> ones only at offset%4==0                            -> word mode
//   bool    -> 0x01 at arbitrary byte offsets                      -> byte mode
// g_gcnt starts at 0 (zero-init on call 1; reset by row_kernel tail after).
// List order varies across replays, but loop 2 takes a set-max -> bit-identical.
// ---------------------------------------------------------------------------
__global__ __launch_bounds__(1024) void prep_kernel(const unsigned char* __restrict__ mraw) {
    __shared__ int s_gt1, s_mis;
    const int t = threadIdx.x;
    if (t == 0) { s_gt1 = 0; s_mis = 0; }
    __syncthreads();

    // flag scan: 19210 words = 4802 uint4 + 2 tail words
    const uint4* m4 = (const uint4*)mraw;
    const unsigned int* mw = (const unsigned int*)mraw;
    unsigned int a = 0, bm = 0;
    for (int i = t; i < 4802; i += 1024) {
        uint4 v = __ldg(m4 + i);
        unsigned int o = v.x | v.y | v.z | v.w;
        a  |= (o & 0xFEFEFEFEu);    // any byte >= 2 anywhere
        bm |= (o & 0x01010100u);    // bit0 set in bytes at offset%4 != 0
    }
    if (t < 2) {
        unsigned int v = __ldg(mw + 19208 + t);
        a  |= (v & 0xFEFEFEFEu);
        bm |= (v & 0x01010100u);
    }
    if (a)  atomicOr(&s_gt1, 1);
    if (bm) atomicOr(&s_mis, 1);
    __syncthreads();
    const int bytemode = (!s_gt1) && s_mis;

    int c = blockIdx.x * 1024 + t;
    if (c >= CC) return;
    unsigned int bits = 0;
    if (bytemode) {
        #pragma unroll
        for (int l = 0; l < LL; ++l)
            if (mraw[l * CC + c] != 0) bits |= (1u << l);
    } else {
        #pragma unroll
        for (int l = 0; l < LL; ++l)
            if (mw[l * CC + c] != 0u) bits |= (1u << l);
    }
    g_gbits[c] = (unsigned char)bits;
    #pragma unroll
    for (int l = 0; l < LL; ++l) {
        if (bits & (1u << l)) {
            int pos = atomicAdd(&g_gcnt[l], 1);
            g_glist[l * CC + pos] = (unsigned short)c;
        }
    }
}

// ---------------------------------------------------------------------------
// row_kernel: one CTA per sample.
// Loop 1: coalesced stream (x float4, y/yn uint4; 2 packs/iter, ALL 6 loads
//   issued unconditionally with clamped index -> MLP_p1 = 6). Candidate
//   detection via pack-max + divergent atomic append (no warp collectives).
//   y/yn positives via integer-OR nonzero test; rare branch -> gbit lookups.
// Loop 2: group-major x-only gathers (L2-hot): 1 fmax per entry.
// Selection: order-invariant rank-count over candidates (exact, deterministic).
// Last CTA reduces partials deterministically and resets g_gcnt/g_done.
// ---------------------------------------------------------------------------
__global__ __launch_bounds__(NT) void row_kernel(const float* __restrict__ x,
                                                 const float* __restrict__ y,
                                                 const float* __restrict__ yn,
                                                 float* __restrict__ out) {
    __shared__ float s_cand[CAP];
    __shared__ float s_red[NT];
    __shared__ float s_gmax[NW][LL];
    __shared__ unsigned int s_gtb[NW], s_gnb[NW];
    __shared__ float s_t16;
    __shared__ int s_ncand, s_last;

    const int b = blockIdx.x, t = threadIdx.x, w = t >> 5, lane = t & 31;
    const size_t base = (size_t)b * CC;
    const float* __restrict__ xr = x + base;
    const float* __restrict__ yr = y + base;
    const float* __restrict__ nr = yn + base;

    // alignment: (b*9605) % 4 == b % 4  (9605 % 4 == 1)
    const int av = b & 3;
    const int p  = (4 - av) & 3;             // scalar peel count
    const int nv = (CC - p) >> 2;            // float4 count
    const int r  = (CC - p) & 3;             // scalar tail count

    if (t == 0) s_ncand = 0;
    __syncthreads();

    const float NI = __int_as_float(0xff800000);
    const unsigned fm = 0xFFFFFFFFu;
    unsigned int gtb = 0, gnb = 0;

    // ---- peel + tail (<= 5 elements; scalar, no collectives) ----
    if (t < p + r) {
        int idx = (t < p) ? t : (p + 4 * nv + (t - p));
        float xv = __ldg(xr + idx);
        if (xv > TVAL) {
            int pos = atomicAdd(&s_ncand, 1);
            if (pos < CAP) s_cand[pos] = xv;
        }
        unsigned int gb = g_gbits[idx];
        if (gb) {
            if (__ldg(yr + idx) > 0.0f) gtb |= gb;
            if (__ldg(nr + idx) > 0.0f) gnb |= gb;
        }
    }

    // ---- Loop 1: coalesced stream, 2 packs/iter, 6 unconditional loads ----
    const float4* __restrict__ x4 = (const float4*)(xr + p);
    const uint4*  __restrict__ yu = (const uint4*)(yr + p);
    const uint4*  __restrict__ nu = (const uint4*)(nr + p);

    // candidate append: pack-max gate, then divergent atomic (rare)
    #define XBLK(XV)                                                           \
    {                                                                          \
        float _pm = fmaxf(fmaxf((XV).x, (XV).y), fmaxf((XV).z, (XV).w));       \
        if (_pm > TVAL) {                                                      \
            int _c = ((XV).x > TVAL) + ((XV).y > TVAL) +                       \
                     ((XV).z > TVAL) + ((XV).w > TVAL);                        \
            int _pos = atomicAdd(&s_ncand, _c);                                \
            if ((XV).x > TVAL) { if (_pos < CAP) s_cand[_pos] = (XV).x; ++_pos; } \
            if ((XV).y > TVAL) { if (_pos < CAP) s_cand[_pos] = (XV).y; ++_pos; } \
            if ((XV).z > TVAL) { if (_pos < CAP) s_cand[_pos] = (XV).z; ++_pos; } \
            if ((XV).w > TVAL) { if (_pos < CAP) s_cand[_pos] = (XV).w; ++_pos; } \
        }                                                                      \
    }

    // positive detection on binarized y/yn: nonzero bit pattern <=> 1.0f
    #define YBLK(YV, VI, DST)                                                  \
    {                                                                          \
        if (((YV).x | (YV).y | (YV).z | (YV).w) != 0u) {                       \
            int _ci = p + 4 * (VI);                                            \
            if ((YV).x) DST |= (unsigned int)g_gbits[_ci];                     \
            if ((YV).y) DST |= (unsigned int)g_gbits[_ci + 1];                 \
            if ((YV).z) DST |= (unsigned int)g_gbits[_ci + 2];                 \
            if ((YV).w) DST |= (unsigned int)g_gbits[_ci + 3];                 \
        }                                                                      \
    }

    for (int v = t; v < nv; v += 2 * NT) {
        const int vb = v + NT;
        const bool hb = (vb < nv);
        const int vbc = hb ? vb : v;             // clamped: load always legal
        float4 xa = __ldg(x4 + v);
        float4 xb = __ldg(x4 + vbc);
        uint4  ya = __ldcs(yu + v);
        uint4  yb = __ldcs(yu + vbc);
        uint4  na = __ldcs(nu + v);
        uint4  nb = __ldcs(nu + vbc);

        XBLK(xa)
        YBLK(ya, v, gtb)
        YBLK(na, v, gnb)
        if (hb) {
            XBLK(xb)
            YBLK(yb, vb, gtb)
            YBLK(nb, vb, gnb)
        }
    }
    #undef XBLK
    #undef YBLK

    // ---- Loop 2: group-major x gathers (L2-hot), 1 fmax per entry ----
    float gmax[LL];
    #pragma unroll
    for (int l = 0; l < LL; ++l) {
        const int cnt = __ldg(&g_gcnt[l]);
        const unsigned short* __restrict__ lst = g_glist + l * CC;
        float m = NI;
        for (int i = t; i < cnt; i += NT)
            m = fmaxf(m, __ldg(xr + (int)__ldg(lst + i)));
        gmax[l] = m;
    }

    // ---- warp-reduce aggregates ----
    #pragma unroll
    for (int off = 16; off > 0; off >>= 1) {
        #pragma unroll
        for (int l = 0; l < LL; ++l)
            gmax[l] = fmaxf(gmax[l], __shfl_xor_sync(fm, gmax[l], off));
        gtb |= __shfl_xor_sync(fm, gtb, off);
        gnb |= __shfl_xor_sync(fm, gnb, off);
    }
    if (lane == 0) {
        #pragma unroll
        for (int l = 0; l < LL; ++l) s_gmax[w][l] = gmax[l];
        s_gtb[w] = gtb;
        s_gnb[w] = gnb;
    }
    __syncthreads();

    int nc = s_ncand;                            // true count of x > TVAL

    // ---- exact fallback (data-independent guarantee): rebuild candidates ----
    if (nc < TOPK || nc > CAP) {
        __syncthreads();                         // everyone done reading s_ncand
        if (t < 64) {
            float tk[TOPK];
            #pragma unroll
            for (int k = 0; k < TOPK; ++k) tk[k] = NI;
            for (int i = t; i < CC; i += 64) {
                float xv = __ldg(xr + i);
                if (xv > tk[TOPK - 1]) {
                    float _v = xv;
                    #pragma unroll
                    for (int k = 0; k < TOPK; ++k)
                        if (_v > tk[k]) { float _tmp = tk[k]; tk[k] = _v; _v = _tmp; }
                }
            }
            #pragma unroll
            for (int k = 0; k < TOPK; ++k) s_cand[t * TOPK + k] = tk[k];
        }
        __syncthreads();
        nc = 64 * TOPK;                          // row top-16 is within these 1024
    }

    // ---- rank-count selection: 16th-largest = v with #{>v} <= 15 < #{>=v} ----
    for (int i = t; i < nc; i += NT) {
        float v = s_cand[i];
        int cg = 0, ce = 0;
        for (int j = 0; j < nc; ++j) {
            float u = s_cand[j];                 // broadcast read, conflict-free
            cg += (u > v);
            ce += (u == v);
        }
        if (cg <= TOPK - 1 && cg + ce >= TOPK) s_t16 = v;   // unique value; benign race
    }
    __syncthreads();

    // ---- per-row loss (thread 0) ----
    if (t == 0) {
        float gmaxA[LL];
        #pragma unroll
        for (int l = 0; l < LL; ++l) gmaxA[l] = NI;
        unsigned int gtA = 0, gnA = 0;
        for (int wv = 0; wv < NW; ++wv) {
            #pragma unroll
            for (int l = 0; l < LL; ++l) gmaxA[l] = fmaxf(gmaxA[l], s_gmax[wv][l]);
            gtA |= s_gtb[wv];
            gnA |= s_gnb[wv];
        }
        float umaxA = NI;                        // union max = max over group maxes
        #pragma unroll
        for (int l = 0; l < LL; ++l) umaxA = fmaxf(umaxA, gmaxA[l]);

        float thres = fmaxf(sigm(s_t16), ALPHA_OTHER);

        float loss;
        if (gtA) {
            loss = 0.0f;
            #pragma unroll
            for (int l = 0; l < LL; ++l) {
                float gm = sigm(gmaxA[l]);
                loss += ((gtA >> l) & 1u) ? rankl(gm, thres)
                                          : rankl(thres, gm);
            }
        } else {
            float um = sigm(umaxA);
            float negs = 0.0f;                   // torch starts at 0
            if (gnA) {
                float nm = NI;
                #pragma unroll
                for (int l = 0; l < LL; ++l)
                    if ((gnA >> l) & 1u) nm = fmaxf(nm, gmaxA[l]);
                negs = sigm(nm);
            }
            loss = (1.0f - ALPHA) * rankl(thres, um) + ALPHA * rankl(thres, negs);
        }
        g_partial[b] = loss;
    }

    // ---- fused deterministic mean: last CTA reduces; resets counters ----
    if (t == 0) {
        __threadfence();
        int old = atomicAdd(&g_done, 1);
        s_last = (old == BB - 1);
    }
    __syncthreads();
    if (s_last) {
        float acc = 0.0f;
        for (int i = t; i < BB; i += NT) acc += g_partial[i];   // fixed order
        s_red[t] = acc;
        __syncthreads();
        for (int st = NT / 2; st > 0; st >>= 1) {
            if (t < st) s_red[t] += s_red[t + st];
            __syncthreads();
        }
        if (t == 0) { out[0] = s_red[0] / (float)BB; g_done = 0; }
        if (t < LL) g_gcnt[t] = 0;               // safe: all CTAs past loop 2
    }
}

extern "C" void kernel_launch(void* const* d_in, const int* in_sizes, int n_in,
                              void* d_out, int out_size) {
    (void)in_sizes; (void)n_in; (void)out_size;
    const float*         x  = (const float*)d_in[0];
    const float*         y  = (const float*)d_in[1];
    const float*         yn = (const float*)d_in[2];
    const unsigned char* m  = (const unsigned char*)d_in[3];

    prep_kernel<<<(CC + 1023) / 1024, 1024>>>(m);
    row_kernel<<<BB, NT>>>(x, y, yn, (float*)d_out);
}